// round 12
// baseline (speedup 1.0000x reference)
#include <cuda_runtime.h>
#include <cuda_bf16.h>
#include <cstdint>

// UVLearner via warp-level bf16 mma.sync (HMMA): S = X^T Y with 3-way bf16
// split (hi*hi + hi*lo + lo*hi), fp32 accum, fused softmax-weighted coord sum.
// R10/R11: 512 threads (4x4 warp grid, 32q x 32k per warp) -> 4 warps/SMSP to
// hide HMMA latency; tensor pipe was 50% idle at 256 threads.
// (R11 resubmit: R10 bench died at container level, result unmeasured.)

#define XROW 272               // 256B row + 16B pad -> conflict-free LDSM
#define SM_XH 0u
#define SM_XL 34816u
#define SM_Y  69632u           // + buf*69632 ; in buf: hi +0, lo +34816
#define SM_RED 208896u         // 4*128*3 floats
#define SMEM_TOTAL 215040u

__device__ uint4 g_yh[4][4096][16];   // y hi-split [b][key][c/8] bf16x8
__device__ uint4 g_yl[4][4096][16];   // y lo-split

__device__ __forceinline__ float ex2(float a) {
    float r; asm("ex2.approx.f32 %0, %1;" : "=f"(r) : "f"(a)); return r;
}
#define LDSM4(r, a) \
    asm volatile("ldmatrix.sync.aligned.m8n8.x4.shared.b16 {%0,%1,%2,%3}, [%4];" \
        : "=r"((r)[0]), "=r"((r)[1]), "=r"((r)[2]), "=r"((r)[3]) : "r"(a))

__device__ __forceinline__ void mma16816(float* c, const uint32_t* a,
                                         const uint32_t* b) {
    asm volatile(
        "mma.sync.aligned.m16n8k16.row.col.f32.bf16.bf16.f32 "
        "{%0,%1,%2,%3}, {%4,%5,%6,%7}, {%8,%9}, {%0,%1,%2,%3};"
        : "+f"(c[0]), "+f"(c[1]), "+f"(c[2]), "+f"(c[3])
        : "r"(a[0]), "r"(a[1]), "r"(a[2]), "r"(a[3]), "r"(b[0]), "r"(b[1]));
}
__device__ __forceinline__ uint32_t pkbf(float v0, float v1) {
    __nv_bfloat16 b0 = __float2bfloat16(v0), b1 = __float2bfloat16(v1);
    return ((uint32_t)__bfloat16_as_ushort(b1) << 16) | __bfloat16_as_ushort(b0);
}

// ---------- pre-pass: y -> [b][k][c] bf16 hi/lo ----------
__global__ __launch_bounds__(256)
void ytrans_kernel(const float* __restrict__ y) {
    int i = blockIdx.x * 256 + threadIdx.x;   // 4 * 16 * 4096
    int k  = i & 4095;
    int cg = (i >> 12) & 15;
    int b  = i >> 16;
    const float* src = y + ((size_t)(b * 128 + cg * 8)) * 4096 + k;
    uint32_t h[4], l[4];
    #pragma unroll
    for (int j = 0; j < 4; j++) {
        float v0 = src[(size_t)(2 * j) * 4096];
        float v1 = src[(size_t)(2 * j + 1) * 4096];
        __nv_bfloat16 h0 = __float2bfloat16(v0);
        __nv_bfloat16 h1 = __float2bfloat16(v1);
        float r0 = v0 - __bfloat162float(h0);
        float r1 = v1 - __bfloat162float(h1);
        h[j] = ((uint32_t)__bfloat16_as_ushort(h1) << 16) | __bfloat16_as_ushort(h0);
        l[j] = pkbf(r0, r1);
    }
    g_yh[b][k][cg] = make_uint4(h[0], h[1], h[2], h[3]);
    g_yl[b][k][cg] = make_uint4(l[0], l[1], l[2], l[3]);
}

// ---------- main kernel ----------
__global__ __launch_bounds__(512, 1)
void uv_kernel(const float* __restrict__ x, float* __restrict__ out) {
    extern __shared__ char smem[];
    const uint32_t sb = (uint32_t)__cvta_generic_to_shared(smem);
    const int tid = threadIdx.x, wid = tid >> 5, lane = tid & 31;
    const int bb = blockIdx.x >> 5, q0 = (blockIdx.x & 31) * 128;
    const float* xb = x + (size_t)bb * 128 * 4096 + q0;
    const float K2E = 0.12754245778362382f;   // log2(e)/sqrt(128)

    // x prologue: scale, split, store [q][c] bf16 rows (hi/lo)
    for (int i = tid; i < 8192; i += 512) {
        int c = (i >> 7) * 2, q = i & 127;
        float v0 = xb[(size_t)c * 4096 + q] * K2E;
        float v1 = xb[(size_t)(c + 1) * 4096 + q] * K2E;
        __nv_bfloat16 h0 = __float2bfloat16(v0), h1 = __float2bfloat16(v1);
        float r0 = v0 - __bfloat162float(h0), r1 = v1 - __bfloat162float(h1);
        uint32_t hp = ((uint32_t)__bfloat16_as_ushort(h1) << 16) | __bfloat16_as_ushort(h0);
        uint32_t lp = pkbf(r0, r1);
        *(uint32_t*)(smem + SM_XH + q * XROW + c * 2) = hp;
        *(uint32_t*)(smem + SM_XL + q * XROW + c * 2) = lp;
    }

    auto prefetch = [&](int t) {
        uint32_t dst0 = sb + SM_Y + (uint32_t)(t & 1) * 69632u;
        for (int i = tid; i < 4096; i += 512) {
            int sp = i >> 11, r = (i >> 4) & 127, j = i & 15;
            uint32_t d = dst0 + (uint32_t)sp * 34816u + (uint32_t)(r * XROW + j * 16);
            const uint4* s = sp ? &g_yl[bb][t * 128 + r][j] : &g_yh[bb][t * 128 + r][j];
            asm volatile("cp.async.ca.shared.global [%0], [%1], 16;"
                         :: "r"(d), "l"(s));
        }
    };

    // warp tiling: 4x4 warps; each warp m = 32 q (2 m16), n = 32 k (4 n8)
    const int mq = (wid & 3) * 32;
    const int nw = wid >> 2;         // 0..3 key-column group
    const int nb = nw * 32;
    const uint32_t aOff = (uint32_t)((mq + (lane & 15)) * XROW + (lane >> 4) * 16);
    // B ldmatrix: row = nb + jp*16 + (lane/16)*8 + lane%8, colb = ks*32 + ((lane>>3)&1)*16
    const uint32_t bOff = (uint32_t)((nb + (lane >> 4) * 8 + (lane & 7)) * XROW
                                     + ((lane >> 3) & 1) * 16);

    float den[4], n0a[4], n1a[4];
    #pragma unroll
    for (int a = 0; a < 4; a++) { den[a] = 0.f; n0a[a] = 0.f; n1a[a] = 0.f; }

    prefetch(0);
    asm volatile("cp.async.commit_group;");
    __syncthreads();   // x tile visible to all warps

    for (int t = 0; t < 32; t++) {
        if (t + 1 < 32) {
            prefetch(t + 1);
            asm volatile("cp.async.commit_group;");
            asm volatile("cp.async.wait_group 1;" ::: "memory");
        } else {
            asm volatile("cp.async.wait_group 0;" ::: "memory");
        }
        __syncthreads();
        const uint32_t ybuf = sb + SM_Y + (uint32_t)(t & 1) * 69632u;
        const uint32_t bhB = ybuf + bOff, blB = bhB + 34816u;
        const uint32_t ahB = sb + SM_XH + aOff, alB = sb + SM_XL + aOff;

        float cA[2][4][4];
        #pragma unroll
        for (int m = 0; m < 2; m++)
            #pragma unroll
            for (int j = 0; j < 4; j++)
                #pragma unroll
                for (int e = 0; e < 4; e++) cA[m][j][e] = 0.f;

        #pragma unroll
        for (int ks = 0; ks < 8; ks++) {
            uint32_t ah[2][4], al[2][4];
            LDSM4(ah[0], ahB + ks * 32);
            LDSM4(ah[1], ahB + ks * 32 + 16 * XROW);
            LDSM4(al[0], alB + ks * 32);
            LDSM4(al[1], alB + ks * 32 + 16 * XROW);
            #pragma unroll
            for (int jp = 0; jp < 2; jp++) {
                uint32_t bh[4], bl[4];
                LDSM4(bh, bhB + jp * (16 * XROW) + ks * 32);
                LDSM4(bl, blB + jp * (16 * XROW) + ks * 32);
                #pragma unroll
                for (int m = 0; m < 2; m++)
                    #pragma unroll
                    for (int jn = 0; jn < 2; jn++) {
                        float* cc = cA[m][2 * jp + jn];
                        mma16816(cc, ah[m], bh + 2 * jn);   // hi*hi
                        mma16816(cc, ah[m], bl + 2 * jn);   // hi*lo
                        mma16816(cc, al[m], bh + 2 * jn);   // lo*hi
                    }
            }
        }
        __syncthreads();   // y buffer free before its overwrite next iter

        // epilogue: key_local = nb + j*8 + 2*(lane&3)+{0,1};
        // grid col = key_local & 63 = (nb&32) + j*8 + 2*(lane&3)+{0,1};
        // grid row = 2t + (nb>=64), warp-constant.
        const float rowc = (float)(2 * t + (nb >> 6)) + 0.5f;
        const float colb = (float)((nb & 32) + 2 * (lane & 3)) + 0.5f;
        #pragma unroll
        for (int m = 0; m < 2; m++)
            #pragma unroll
            for (int h = 0; h < 2; h++) {
                float dt = 0.f, n0t = 0.f;
                #pragma unroll
                for (int j = 0; j < 4; j++) {
                    float e0 = ex2(cA[m][j][2 * h]);
                    float e1 = ex2(cA[m][j][2 * h + 1]);
                    float k0 = colb + (float)(j * 8);
                    dt += e0 + e1;
                    n0t = fmaf(e0, k0, n0t);
                    n0t = fmaf(e1, k0 + 1.0f, n0t);
                }
                int a = m * 2 + h;
                den[a] += dt;
                n0a[a] += n0t;
                n1a[a] = fmaf(dt, rowc, n1a[a]);
            }
    }

    // reduce across the 4 lanes of each row group
    #pragma unroll
    for (int a = 0; a < 4; a++) {
        #pragma unroll
        for (int off = 1; off < 4; off <<= 1) {
            den[a] += __shfl_xor_sync(0xffffffffu, den[a], off, 4);
            n0a[a] += __shfl_xor_sync(0xffffffffu, n0a[a], off, 4);
            n1a[a] += __shfl_xor_sync(0xffffffffu, n1a[a], off, 4);
        }
    }
    float* red = (float*)(smem + SM_RED);
    if ((lane & 3) == 0) {
        #pragma unroll
        for (int a = 0; a < 4; a++) {
            int qrow = mq + (a >> 1) * 16 + (lane >> 2) + (a & 1) * 8;
            int base = (nw * 128 + qrow) * 3;
            red[base] = den[a]; red[base + 1] = n0a[a]; red[base + 2] = n1a[a];
        }
    }
    __syncthreads();

    if (tid < 128) {
        float d = 0.f, n0 = 0.f, n1 = 0.f;
        #pragma unroll
        for (int w = 0; w < 4; w++) {
            int base = (w * 128 + tid) * 3;
            d  += red[base];
            n0 += red[base + 1];
            n1 += red[base + 2];
        }
        float inv = 1.0f / (32.0f * d);   // (uv/64)*2 - 1
        float* o = out + ((size_t)bb * 4096 + q0 + tid) * 2;
        o[0] = n0 * inv - 1.0f;
        o[1] = n1 * inv - 1.0f;
    }
}

extern "C" void kernel_launch(void* const* d_in, const int* in_sizes, int n_in,
                              void* d_out, int out_size) {
    const float* x = (const float*)d_in[0];
    const float* y = (const float*)d_in[1];
    float* out = (float*)d_out;

    cudaFuncSetAttribute(uv_kernel,
                         cudaFuncAttributeMaxDynamicSharedMemorySize,
                         (int)SMEM_TOTAL);
    ytrans_kernel<<<1024, 256>>>(y);
    uv_kernel<<<128, 512, SMEM_TOTAL>>>(x, out);
}

// round 13
// speedup vs baseline: 2.1011x; 2.1011x over previous
#include <cuda_runtime.h>
#include <cuda_fp16.h>
#include <cstdint>

// UVLearner via warp-level fp16 mma.sync: S = X^T Y in ONE fp16 MMA pass.
// Rationale: exact-fp32 kernels score rel_err 3.5e-4 vs this reference ->
// the reference itself is tf32-precision (11-bit mantissa). fp16 has the
// same 11-bit mantissa, so a single unsplit fp16 MMA adds ~4e-4 error in
// quadrature (total ~5.5e-4 < 1e-3) while cutting tensor work 3x vs the
// R10 bf16 3-way split.

#define XROW 272               // 256B row + 16B pad -> conflict-free LDSM
#define SM_X  0u
#define SM_Y  34816u           // + buf*34816
#define SM_RED 104448u         // 4*128*3 floats
#define SMEM_TOTAL 110592u

__device__ uint4 g_y[4][4096][16];   // y fp16 [b][key][c/8] half2 x8

__device__ __forceinline__ float ex2(float a) {
    float r; asm("ex2.approx.f32 %0, %1;" : "=f"(r) : "f"(a)); return r;
}
#define LDSM4(r, a) \
    asm volatile("ldmatrix.sync.aligned.m8n8.x4.shared.b16 {%0,%1,%2,%3}, [%4];" \
        : "=r"((r)[0]), "=r"((r)[1]), "=r"((r)[2]), "=r"((r)[3]) : "r"(a))

__device__ __forceinline__ void mma16816(float* c, const uint32_t* a,
                                         const uint32_t* b) {
    asm volatile(
        "mma.sync.aligned.m16n8k16.row.col.f32.f16.f16.f32 "
        "{%0,%1,%2,%3}, {%4,%5,%6,%7}, {%8,%9}, {%0,%1,%2,%3};"
        : "+f"(c[0]), "+f"(c[1]), "+f"(c[2]), "+f"(c[3])
        : "r"(a[0]), "r"(a[1]), "r"(a[2]), "r"(a[3]), "r"(b[0]), "r"(b[1]));
}
__device__ __forceinline__ uint32_t pkh(float v0, float v1) {
    __half h0 = __float2half_rn(v0), h1 = __float2half_rn(v1);
    return ((uint32_t)__half_as_ushort(h1) << 16) | __half_as_ushort(h0);
}

// ---------- pre-pass: y -> [b][k][c] fp16 ----------
__global__ __launch_bounds__(256)
void ytrans_kernel(const float* __restrict__ y) {
    int i = blockIdx.x * 256 + threadIdx.x;   // 4 * 16 * 4096
    int k  = i & 4095;
    int cg = (i >> 12) & 15;
    int b  = i >> 16;
    const float* src = y + ((size_t)(b * 128 + cg * 8)) * 4096 + k;
    uint32_t h[4];
    #pragma unroll
    for (int j = 0; j < 4; j++)
        h[j] = pkh(src[(size_t)(2 * j) * 4096], src[(size_t)(2 * j + 1) * 4096]);
    g_y[b][k][cg] = make_uint4(h[0], h[1], h[2], h[3]);
}

// ---------- main kernel ----------
__global__ __launch_bounds__(512, 1)
void uv_kernel(const float* __restrict__ x, float* __restrict__ out) {
    extern __shared__ char smem[];
    const uint32_t sb = (uint32_t)__cvta_generic_to_shared(smem);
    const int tid = threadIdx.x, wid = tid >> 5, lane = tid & 31;
    const int bb = blockIdx.x >> 5, q0 = (blockIdx.x & 31) * 128;
    const float* xb = x + (size_t)bb * 128 * 4096 + q0;
    const float K2E = 0.12754245778362382f;   // log2(e)/sqrt(128)

    // x prologue: scale + fp16, store [q][c] rows
    for (int i = tid; i < 8192; i += 512) {
        int c = (i >> 7) * 2, q = i & 127;
        float v0 = xb[(size_t)c * 4096 + q] * K2E;
        float v1 = xb[(size_t)(c + 1) * 4096 + q] * K2E;
        *(uint32_t*)(smem + SM_X + q * XROW + c * 2) = pkh(v0, v1);
    }

    auto prefetch = [&](int t) {
        uint32_t dst0 = sb + SM_Y + (uint32_t)(t & 1) * 34816u;
        for (int i = tid; i < 2048; i += 512) {
            int r = i >> 4, j = i & 15;
            uint32_t d = dst0 + (uint32_t)(r * XROW + j * 16);
            const uint4* s = &g_y[bb][t * 128 + r][j];
            asm volatile("cp.async.ca.shared.global [%0], [%1], 16;"
                         :: "r"(d), "l"(s));
        }
    };

    // warp tiling: 4x4 warps; each warp m = 32 q (2 m16), n = 32 k (4 n8)
    const int mq = (wid & 3) * 32;
    const int nw = wid >> 2;
    const int nb = nw * 32;
    const uint32_t aOff = (uint32_t)((mq + (lane & 15)) * XROW + (lane >> 4) * 16);
    const uint32_t bOff = (uint32_t)((nb + (lane >> 4) * 8 + (lane & 7)) * XROW
                                     + ((lane >> 3) & 1) * 16);

    float den[4], n0a[4], n1a[4];
    #pragma unroll
    for (int a = 0; a < 4; a++) { den[a] = 0.f; n0a[a] = 0.f; n1a[a] = 0.f; }

    prefetch(0);
    asm volatile("cp.async.commit_group;");
    __syncthreads();   // x tile visible to all warps

    for (int t = 0; t < 32; t++) {
        if (t + 1 < 32) {
            prefetch(t + 1);
            asm volatile("cp.async.commit_group;");
            asm volatile("cp.async.wait_group 1;" ::: "memory");
        } else {
            asm volatile("cp.async.wait_group 0;" ::: "memory");
        }
        __syncthreads();
        const uint32_t ybuf = sb + SM_Y + (uint32_t)(t & 1) * 34816u;
        const uint32_t bB = ybuf + bOff;
        const uint32_t aB = sb + SM_X + aOff;

        float cA[2][4][4];
        #pragma unroll
        for (int m = 0; m < 2; m++)
            #pragma unroll
            for (int j = 0; j < 4; j++)
                #pragma unroll
                for (int e = 0; e < 4; e++) cA[m][j][e] = 0.f;

        #pragma unroll
        for (int ks = 0; ks < 8; ks++) {
            uint32_t ah[2][4];
            LDSM4(ah[0], aB + ks * 32);
            LDSM4(ah[1], aB + ks * 32 + 16 * XROW);
            #pragma unroll
            for (int jp = 0; jp < 2; jp++) {
                uint32_t bh[4];
                LDSM4(bh, bB + jp * (16 * XROW) + ks * 32);
                #pragma unroll
                for (int m = 0; m < 2; m++)
                    #pragma unroll
                    for (int jn = 0; jn < 2; jn++)
                        mma16816(cA[m][2 * jp + jn], ah[m], bh + 2 * jn);
            }
        }
        __syncthreads();   // y buffer free before its overwrite next iter

        // epilogue: key_local = nb + j*8 + 2*(lane&3)+{0,1};
        // grid col = (nb&32) + j*8 + 2*(lane&3)+{0,1}; row = 2t + (nb>=64).
        const float rowc = (float)(2 * t + (nb >> 6)) + 0.5f;
        const float colb = (float)((nb & 32) + 2 * (lane & 3)) + 0.5f;
        #pragma unroll
        for (int m = 0; m < 2; m++)
            #pragma unroll
            for (int h = 0; h < 2; h++) {
                float dt = 0.f, n0t = 0.f;
                #pragma unroll
                for (int j = 0; j < 4; j++) {
                    float e0 = ex2(cA[m][j][2 * h]);
                    float e1 = ex2(cA[m][j][2 * h + 1]);
                    float k0 = colb + (float)(j * 8);
                    dt += e0 + e1;
                    n0t = fmaf(e0, k0, n0t);
                    n0t = fmaf(e1, k0 + 1.0f, n0t);
                }
                int a = m * 2 + h;
                den[a] += dt;
                n0a[a] += n0t;
                n1a[a] = fmaf(dt, rowc, n1a[a]);
            }
    }

    // reduce across the 4 lanes of each row group
    #pragma unroll
    for (int a = 0; a < 4; a++) {
        #pragma unroll
        for (int off = 1; off < 4; off <<= 1) {
            den[a] += __shfl_xor_sync(0xffffffffu, den[a], off, 4);
            n0a[a] += __shfl_xor_sync(0xffffffffu, n0a[a], off, 4);
            n1a[a] += __shfl_xor_sync(0xffffffffu, n1a[a], off, 4);
        }
    }
    float* red = (float*)(smem + SM_RED);
    if ((lane & 3) == 0) {
        #pragma unroll
        for (int a = 0; a < 4; a++) {
            int qrow = mq + (a >> 1) * 16 + (lane >> 2) + (a & 1) * 8;
            int base = (nw * 128 + qrow) * 3;
            red[base] = den[a]; red[base + 1] = n0a[a]; red[base + 2] = n1a[a];
        }
    }
    __syncthreads();

    if (tid < 128) {
        float d = 0.f, n0 = 0.f, n1 = 0.f;
        #pragma unroll
        for (int w = 0; w < 4; w++) {
            int base = (w * 128 + tid) * 3;
            d  += red[base];
            n0 += red[base + 1];
            n1 += red[base + 2];
        }
        float inv = 1.0f / (32.0f * d);   // (uv/64)*2 - 1
        float* o = out + ((size_t)bb * 4096 + q0 + tid) * 2;
        o[0] = n0 * inv - 1.0f;
        o[1] = n1 * inv - 1.0f;
    }
}

extern "C" void kernel_launch(void* const* d_in, const int* in_sizes, int n_in,
                              void* d_out, int out_size) {
    const float* x = (const float*)d_in[0];
    const float* y = (const float*)d_in[1];
    float* out = (float*)d_out;

    cudaFuncSetAttribute(uv_kernel,
                         cudaFuncAttributeMaxDynamicSharedMemorySize,
                         (int)SMEM_TOTAL);
    ytrans_kernel<<<1024, 256>>>(y);
    uv_kernel<<<128, 512, SMEM_TOTAL>>>(x, out);
}

// round 15
// speedup vs baseline: 2.4270x; 1.1551x over previous
#include <cuda_runtime.h>
#include <cuda_fp16.h>
#include <cstdint>

// UVLearner, fp16 mma.sync. R13 -> R14:
//  - A (query) fragments persistent in registers: loaded once, 0 LDSM/tile
//  - 3-deep Y buffer ring, single __syncthreads per tile
//  - packed f32x2 epilogue accumulation
// 8 warps (4 q-groups x 2 k-groups), each 32q x 64k per tile.

#define XROW 272               // 256B row + 16B pad -> conflict-free LDSM
#define SM_X  0u
#define SM_Y  34816u           // 3 buffers x 34816
#define SM_RED 139264u         // 2*128*3 floats
#define SMEM_TOTAL 142336u

__device__ uint4 g_y[4][4096][16];   // y fp16 [b][key][c/8] half2 x8

__device__ __forceinline__ float ex2(float a) {
    float r; asm("ex2.approx.f32 %0, %1;" : "=f"(r) : "f"(a)); return r;
}
__device__ __forceinline__ unsigned long long pk2(float lo, float hi) {
    unsigned long long r;
    asm("mov.b64 %0, {%1, %2};" : "=l"(r) : "f"(lo), "f"(hi));
    return r;
}
__device__ __forceinline__ void upk2(float& lo, float& hi, unsigned long long v) {
    asm("mov.b64 {%0, %1}, %2;" : "=f"(lo), "=f"(hi) : "l"(v));
}
__device__ __forceinline__ unsigned long long ffma2(unsigned long long a,
                                                    unsigned long long b,
                                                    unsigned long long c) {
    unsigned long long d;
    asm("fma.rn.f32x2 %0, %1, %2, %3;" : "=l"(d) : "l"(a), "l"(b), "l"(c));
    return d;
}
#define LDSM4(r, a) \
    asm volatile("ldmatrix.sync.aligned.m8n8.x4.shared.b16 {%0,%1,%2,%3}, [%4];" \
        : "=r"((r)[0]), "=r"((r)[1]), "=r"((r)[2]), "=r"((r)[3]) : "r"(a))

__device__ __forceinline__ void mma16816(float* c, const uint32_t* a,
                                         const uint32_t* b) {
    asm volatile(
        "mma.sync.aligned.m16n8k16.row.col.f32.f16.f16.f32 "
        "{%0,%1,%2,%3}, {%4,%5,%6,%7}, {%8,%9}, {%0,%1,%2,%3};"
        : "+f"(c[0]), "+f"(c[1]), "+f"(c[2]), "+f"(c[3])
        : "r"(a[0]), "r"(a[1]), "r"(a[2]), "r"(a[3]), "r"(b[0]), "r"(b[1]));
}
__device__ __forceinline__ uint32_t pkh(float v0, float v1) {
    __half h0 = __float2half_rn(v0), h1 = __float2half_rn(v1);
    return ((uint32_t)__half_as_ushort(h1) << 16) | __half_as_ushort(h0);
}

// ---------- pre-pass: y -> [b][k][c] fp16 ----------
__global__ __launch_bounds__(256)
void ytrans_kernel(const float* __restrict__ y) {
    int i = blockIdx.x * 256 + threadIdx.x;   // 4 * 16 * 4096
    int k  = i & 4095;
    int cg = (i >> 12) & 15;
    int b  = i >> 16;
    const float* src = y + ((size_t)(b * 128 + cg * 8)) * 4096 + k;
    uint32_t h[4];
    #pragma unroll
    for (int j = 0; j < 4; j++)
        h[j] = pkh(src[(size_t)(2 * j) * 4096], src[(size_t)(2 * j + 1) * 4096]);
    g_y[b][k][cg] = make_uint4(h[0], h[1], h[2], h[3]);
}

// ---------- main kernel ----------
__global__ __launch_bounds__(256, 1)
void uv_kernel(const float* __restrict__ x, float* __restrict__ out) {
    extern __shared__ char smem[];
    const uint32_t sb = (uint32_t)__cvta_generic_to_shared(smem);
    const int tid = threadIdx.x, wid = tid >> 5, lane = tid & 31;
    const int bb = blockIdx.x >> 5, q0 = (blockIdx.x & 31) * 128;
    const float* xb = x + (size_t)bb * 128 * 4096 + q0;
    const float K2E = 0.12754245778362382f;   // log2(e)/sqrt(128)

    auto prefetch = [&](int t) {
        uint32_t dst0 = sb + SM_Y + (uint32_t)(t % 3) * 34816u;
        #pragma unroll
        for (int i = tid; i < 2048; i += 256) {
            int r = i >> 4, j = i & 15;
            uint32_t d = dst0 + (uint32_t)(r * XROW + j * 16);
            const uint4* s = &g_y[bb][t * 128 + r][j];
            asm volatile("cp.async.ca.shared.global [%0], [%1], 16;"
                         :: "r"(d), "l"(s));
        }
    };

    prefetch(0);
    asm volatile("cp.async.commit_group;");
    prefetch(1);
    asm volatile("cp.async.commit_group;");

    // x prologue: scale + fp16, store [q][c] rows
    for (int i = tid; i < 8192; i += 256) {
        int c = (i >> 7) * 2, q = i & 127;
        float v0 = xb[(size_t)c * 4096 + q] * K2E;
        float v1 = xb[(size_t)(c + 1) * 4096 + q] * K2E;
        *(uint32_t*)(smem + SM_X + q * XROW + c * 2) = pkh(v0, v1);
    }
    __syncthreads();

    // warp tiling: 8 warps = 4 q-groups x 2 k-groups; 32q x 64k per warp
    const int mq = (wid & 3) * 32;
    const int nw = wid >> 2;          // 0..1
    const int nb = nw * 64;
    const uint32_t aB = sb + SM_X
        + (uint32_t)((mq + (lane & 15)) * XROW + (lane >> 4) * 16);
    const uint32_t bOff = (uint32_t)((nb + (lane >> 4) * 8 + (lane & 7)) * XROW
                                     + ((lane >> 3) & 1) * 16);

    // persistent A fragments: 32q x 128c, loaded once (64 regs)
    uint32_t ah[8][2][4];
    #pragma unroll
    for (int ks = 0; ks < 8; ks++) {
        LDSM4(ah[ks][0], aB + ks * 32);
        LDSM4(ah[ks][1], aB + ks * 32 + 16 * XROW);
    }

    unsigned long long den2[4], n02[4], n12[4], col2[8];
    const unsigned long long one2 = pk2(1.0f, 1.0f);
    #pragma unroll
    for (int a = 0; a < 4; a++) { den2[a] = 0ull; n02[a] = 0ull; n12[a] = 0ull; }
    #pragma unroll
    for (int j = 0; j < 8; j++) {
        float c0 = (float)(j * 8 + 2 * (lane & 3)) + 0.5f;   // nb mod 64 drops out
        col2[j] = pk2(c0, c0 + 1.0f);
    }

    for (int t = 0; t < 32; t++) {
        if (t < 31) asm volatile("cp.async.wait_group 1;" ::: "memory");
        else        asm volatile("cp.async.wait_group 0;" ::: "memory");
        __syncthreads();
        if (t + 2 < 32) {
            prefetch(t + 2);
            asm volatile("cp.async.commit_group;");
        }
        const uint32_t bB = sb + SM_Y + (uint32_t)(t % 3) * 34816u + bOff;

        float cA[2][8][4];
        #pragma unroll
        for (int m = 0; m < 2; m++)
            #pragma unroll
            for (int j = 0; j < 8; j++)
                #pragma unroll
                for (int e = 0; e < 4; e++) cA[m][j][e] = 0.f;

        #pragma unroll
        for (int ks = 0; ks < 8; ks++) {
            uint32_t bf[4][4];
            LDSM4(bf[0], bB + ks * 32);
            LDSM4(bf[1], bB + ks * 32 + 16 * XROW);
            LDSM4(bf[2], bB + ks * 32 + 32 * XROW);
            LDSM4(bf[3], bB + ks * 32 + 48 * XROW);
            #pragma unroll
            for (int m = 0; m < 2; m++)
                #pragma unroll
                for (int jb = 0; jb < 4; jb++) {
                    mma16816(cA[m][2 * jb],     ah[ks][m], bf[jb]);
                    mma16816(cA[m][2 * jb + 1], ah[ks][m], bf[jb] + 2);
                }
        }

        // epilogue (packed): key rows 0..63 of this warp are grid row 2t+nw
        const float rowc = (float)(2 * t + nw) + 0.5f;
        const unsigned long long row2 = pk2(rowc, rowc);
        #pragma unroll
        for (int m = 0; m < 2; m++)
            #pragma unroll
            for (int h = 0; h < 2; h++) {
                int a = m * 2 + h;
                #pragma unroll
                for (int j = 0; j < 8; j++) {
                    unsigned long long e2 =
                        pk2(ex2(cA[m][j][2 * h]), ex2(cA[m][j][2 * h + 1]));
                    den2[a] = ffma2(e2, one2,    den2[a]);
                    n02[a]  = ffma2(e2, col2[j], n02[a]);
                    n12[a]  = ffma2(e2, row2,    n12[a]);
                }
            }
    }

    // fold packed halves, reduce across the 4 lanes of each row group
    float* red = (float*)(smem + SM_RED);
    #pragma unroll
    for (int a = 0; a < 4; a++) {
        float dl, dh, al, ah2, bl, bh;
        upk2(dl, dh, den2[a]);
        upk2(al, ah2, n02[a]);
        upk2(bl, bh, n12[a]);
        float den = dl + dh, n0 = al + ah2, n1 = bl + bh;
        #pragma unroll
        for (int off = 1; off < 4; off <<= 1) {
            den += __shfl_xor_sync(0xffffffffu, den, off, 4);
            n0  += __shfl_xor_sync(0xffffffffu, n0,  off, 4);
            n1  += __shfl_xor_sync(0xffffffffu, n1,  off, 4);
        }
        if ((lane & 3) == 0) {
            int qrow = mq + (a >> 1) * 16 + (lane >> 2) + (a & 1) * 8;
            int base = (nw * 128 + qrow) * 3;
            red[base] = den; red[base + 1] = n0; red[base + 2] = n1;
        }
    }
    __syncthreads();

    if (tid < 128) {
        float d  = red[tid * 3]     + red[(128 + tid) * 3];
        float n0 = red[tid * 3 + 1] + red[(128 + tid) * 3 + 1];
        float n1 = red[tid * 3 + 2] + red[(128 + tid) * 3 + 2];
        float inv = 1.0f / (32.0f * d);   // (uv/64)*2 - 1
        float* o = out + ((size_t)bb * 4096 + q0 + tid) * 2;
        o[0] = n0 * inv - 1.0f;
        o[1] = n1 * inv - 1.0f;
    }
}

extern "C" void kernel_launch(void* const* d_in, const int* in_sizes, int n_in,
                              void* d_out, int out_size) {
    const float* x = (const float*)d_in[0];
    const float* y = (const float*)d_in[1];
    float* out = (float*)d_out;

    cudaFuncSetAttribute(uv_kernel,
                         cudaFuncAttributeMaxDynamicSharedMemorySize,
                         (int)SMEM_TOTAL);
    ytrans_kernel<<<1024, 256>>>(y);
    uv_kernel<<<128, 256, SMEM_TOTAL>>>(x, out);
}